// round 15
// baseline (speedup 1.0000x reference)
#include <cuda_runtime.h>
#include <cstdint>

#define TT   1000
#define TM1  999
#define BB   64

__device__ float g_tau[256], g_lam[256], g_AtL[256], g_AtLA[256];
__device__ float g_tau_mu[16], g_AtLb[16], g_Lb[16];
__device__ float g_consts[2];
__device__ unsigned g_keys[BB][2];

__device__ float g_scr1[(size_t)BB * TM1 * 256]; // fwd: Pi   -> bwd: K^T
__device__ float g_scr2[(size_t)BB * TM1 * 256]; // fwd: G    -> bwd: Ls
__device__ float g_scr3[(size_t)BB * TT  * 16];  // fwd: Mim  -> bwd: m_t (slot TM1=m_T)
__device__ float g_eps [(size_t)BB * TT  * 16];

__device__ __forceinline__ void tf2x32(unsigned k0, unsigned k1,
                                       unsigned x0, unsigned x1,
                                       unsigned &o0, unsigned &o1) {
    unsigned ks2 = k0 ^ k1 ^ 0x1BD11BDAu;
    x0 += k0; x1 += k1;
#define TFR(r) { x0 += x1; x1 = (x1 << (r)) | (x1 >> (32 - (r))); x1 ^= x0; }
    TFR(13) TFR(15) TFR(26) TFR(6)
    x0 += k1;  x1 += ks2 + 1u;
    TFR(17) TFR(29) TFR(16) TFR(24)
    x0 += ks2; x1 += k0 + 2u;
    TFR(13) TFR(15) TFR(26) TFR(6)
    x0 += k0;  x1 += k1 + 3u;
    TFR(17) TFR(29) TFR(16) TFR(24)
    x0 += k1;  x1 += ks2 + 4u;
    TFR(13) TFR(15) TFR(26) TFR(6)
    x0 += ks2; x1 += k0 + 5u;
#undef TFR
    o0 = x0; o1 = x1;
}

// ---- blocked GJ, 2 pivots [k,k+1], augmented [M(16)|R(16)|m]; C->N; sync; returns det ----
template <bool WITH_M>
__device__ __forceinline__ float gj_block2(const float (*C)[48], float (*N)[48],
                                           int k, int i, int j) {
    float p00 = C[k][k],     p01 = C[k][k + 1];
    float p10 = C[k + 1][k], p11 = C[k + 1][k + 1];
    float det = p00 * p11 - p01 * p10;
    float id  = __fdividef(1.f, det);
    float Di00 =  p11 * id, Di01 = -p01 * id;
    float Di10 = -p10 * id, Di11 =  p00 * id;
    float u0 = C[i][k], u1 = C[i][k + 1];

    // left column j
    {
        float res;
        if (j == k || j == k + 1) {
            float c0 = (j == k) ? Di00 : Di01;   // row k
            float c1 = (j == k) ? Di10 : Di11;   // row k+1
            if (i == k)          res = c0;
            else if (i == k + 1) res = c1;
            else                 res = -(u0 * c0 + u1 * c1);
        } else {
            float b0 = C[k][j], b1 = C[k + 1][j];
            float w0 = Di00 * b0 + Di01 * b1;
            float w1 = Di10 * b0 + Di11 * b1;
            if (i == k)          res = w0;
            else if (i == k + 1) res = w1;
            else                 res = C[i][j] - (u0 * w0 + u1 * w1);
        }
        N[i][j] = res;
    }
    // right column j+16 (never a pivot column)
    {
        float b0 = C[k][j + 16], b1 = C[k + 1][j + 16];
        float w0 = Di00 * b0 + Di01 * b1;
        float w1 = Di10 * b0 + Di11 * b1;
        float res;
        if (i == k)          res = w0;
        else if (i == k + 1) res = w1;
        else                 res = C[i][j + 16] - (u0 * w0 + u1 * w1);
        N[i][j + 16] = res;
    }
    if (WITH_M && j == 0) {
        float b0 = C[k][32], b1 = C[k + 1][32];
        float w0 = Di00 * b0 + Di01 * b1;
        float w1 = Di10 * b0 + Di11 * b1;
        float res;
        if (i == k)          res = w0;
        else if (i == k + 1) res = w1;
        else                 res = C[i][32] - (u0 * w0 + u1 * w1);
        N[i][32] = res;
    }
    __syncthreads();
    return det;
}

// ---- blocked Cholesky (lower), 2 columns [k,k+1]; C->N (left 16 cols); sync ----
__device__ __forceinline__ void chol_block2(const float (*C)[48], float (*N)[48],
                                            int k, int i, int j) {
    float r0  = rsqrtf(C[k][k]);
    float l10 = C[k + 1][k] * r0;
    float t11 = C[k + 1][k + 1] - l10 * l10;
    float r1  = rsqrtf(t11);

    float res = C[i][j];
    if (j >= k) {
        float p0 = C[i][k] * r0;
        float p1 = (C[i][k + 1] - p0 * l10) * r1;
        if (j == k) {
            if (i >= k) res = p0;
        } else if (j == k + 1) {
            if (i >= k + 1) res = p1;
        } else if (i >= j) {
            float q0 = C[j][k] * r0;
            float q1 = (C[j][k + 1] - q0 * l10) * r1;
            res = res - p0 * q0 - p1 * q1;
        }
    }
    N[i][j] = res;
    __syncthreads();
}

__device__ float logdet16_local(const float M[16][17]) {
    float a[16][16];
    for (int r = 0; r < 16; ++r)
        for (int c = 0; c < 16; ++c) a[r][c] = M[r][c];
    float ld = 0.f;
    for (int k = 0; k < 16; ++k) {
        float p = a[k][k];
        ld += logf(p);
        float pi_ = __fdiv_rn(1.f, p);
        for (int r = k + 1; r < 16; ++r) {
            float f = a[r][k] * pi_;
            for (int c = k + 1; c < 16; ++c) a[r][c] = fmaf(-f, a[k][c], a[r][c]);
        }
    }
    return ld;
}

__global__ void __launch_bounds__(256) setup_kernel(const float* __restrict__ loc,
                                                    const float* __restrict__ Tau_p,
                                                    const float* __restrict__ Lam_p,
                                                    const float* __restrict__ X) {
    __shared__ float sTau[16][17], sLamS[16][17], sA[16][17], sAtLs[16][17];
    __shared__ float sbv[16], slocv[16];
    int tid = threadIdx.x, i = tid >> 4, j = tid & 15;

    float t = 0.f, l = 0.f;
#pragma unroll
    for (int k = 0; k < 16; ++k) {
        t = fmaf(Tau_p[i * 16 + k], Tau_p[j * 16 + k], t);
        l = fmaf(Lam_p[i * 16 + k], Lam_p[j * 16 + k], l);
    }
    if (i == j) { t += 1e-8f; l += 1e-8f; }
    sTau[i][j] = t; sLamS[i][j] = l;
    sA[i][j]   = X[i * 17 + j];
    if (tid < 16) { sbv[tid] = X[tid * 17 + 16]; slocv[tid] = loc[tid]; }
    __syncthreads();

    float atl = 0.f;
#pragma unroll
    for (int k = 0; k < 16; ++k) atl = fmaf(sA[k][i], sLamS[k][j], atl);
    sAtLs[i][j] = atl;
    __syncthreads();

    float atla = 0.f;
#pragma unroll
    for (int k = 0; k < 16; ++k) atla = fmaf(sAtLs[i][k], sA[k][j], atla);

    g_tau[tid] = t; g_lam[tid] = l; g_AtL[tid] = atl; g_AtLA[tid] = atla;

    if (tid < 16) {
        float tm = 0.f, alb = 0.f, lb = 0.f;
#pragma unroll
        for (int k = 0; k < 16; ++k) {
            tm  = fmaf(sTau[tid][k],  slocv[k], tm);
            alb = fmaf(sAtLs[tid][k], sbv[k],   alb);
            lb  = fmaf(sLamS[tid][k], sbv[k],   lb);
        }
        g_tau_mu[tid] = tm; g_AtLb[tid] = alb; g_Lb[tid] = lb;
    }
    if (tid < BB) {
        unsigned o0, o1;
        tf2x32(0u, 42u, 0u, (unsigned)tid, o0, o1);
        g_keys[tid][0] = o0; g_keys[tid][1] = o1;
    }
    __syncthreads();
    if (tid == 0) {
        float ldl = logdet16_local(sLamS);
        float ldt = logdet16_local(sTau);
        float bLb = 0.f, ltm = 0.f;
        for (int k = 0; k < 16; ++k) {
            bLb = fmaf(sbv[k],   g_Lb[k],     bLb);
            ltm = fmaf(slocv[k], g_tau_mu[k], ltm);
        }
        g_consts[0] = -0.5f * bLb + 0.5f * ldl;
        g_consts[1] = -0.5f * ltm + 0.5f * ldt;
    }
}

__global__ void __launch_bounds__(256, 1) lds_main(const float* __restrict__ Jr,
                                                   const float* __restrict__ hr,
                                                   float* __restrict__ out) {
    const int b   = blockIdx.x;
    const int tid = threadIdx.x;
    const int i   = tid >> 4, j = tid & 15;
    const bool isdiag = (i == j);
    const bool isv    = (j == 0);

    const float trans_const = g_consts[0];
    const float init_const  = g_consts[1];

    const float* Jb = Jr + (size_t)b * TT * 16;
    const float* Hb = hr + (size_t)b * TT * 16;
    float* scr1 = g_scr1 + (size_t)b * TM1 * 256;
    float* scr2 = g_scr2 + (size_t)b * TM1 * 256;
    float* scr3 = g_scr3 + (size_t)b * TT * 16;
    float* epsb = g_eps  + (size_t)b * TT * 16;

    const size_t KL_OFF    = (size_t)BB * TT * 16;
    const size_t EXXT_OFF  = KL_OFF + BB;
    const size_t EX_OFF    = EXXT_OFF + (size_t)BB * TT * 256;
    const size_t EXXNT_OFF = EX_OFF + (size_t)BB * TT * 16;
    float* zO     = out + (size_t)b * TT * 16;
    float* exxtO  = out + EXXT_OFF + (size_t)b * TT * 256;
    float* exO    = out + EX_OFF + (size_t)b * TT * 16;
    float* exxntO = out + EXXNT_OFF + (size_t)b * TM1 * 256;

    __shared__ float Buf0[16][48], Buf1[16][48];
    __shared__ float sAtL[16][17];
    __shared__ float Gm[16][17], Wb[16][17], Vn[16][17];
    __shared__ float mt_s[16], mn[16], mT_s[16];
    __shared__ float xs[2][16];
    __shared__ float red[32];

    // ---- epsilon generation ----
    {
        unsigned k0 = g_keys[b][0], k1 = g_keys[b][1];
        for (int idx = tid; idx < TT * 16; idx += 256) {
            unsigned o0, o1;
            tf2x32(k0, k1, 0u, (unsigned)idx, o0, o1);
            unsigned bits = o0 ^ o1;
            float f = __uint_as_float((bits >> 9) | 0x3f800000u) - 1.0f;
            const float lo = -0.99999994f;
            float v = fmaxf(lo, f * 2.0f + lo);
            epsb[idx] = 1.4142135623730951f * erfinvf(v);
        }
    }

    const float lam_r  = g_lam[tid];
    const float atla_r = g_AtLA[tid];
    const float atl_r  = g_AtL[tid];
    sAtL[i][j] = atl_r;
    const float lb_r   = g_Lb[i];
    const float atlb_r = g_AtLb[i];

    float lzall = 0.f;       // all threads (identical)
    float lzp   = 0.f;       // j==0 threads
    float klacc = 0.f;       // diag threads
    float jn_r = 0.f, hn_r = 0.f;
    float mv_r = 0.f;

    // ---- pre-stage step 0 ----
    {
        float fJ0 = g_tau[tid] + (isdiag ? (Jb[i] + 0.5f) : 0.f);
        Buf0[i][j]      = fJ0 + atla_r;
        Buf0[i][j + 16] = atl_r;
        if (isv) {
            float fh0 = g_tau_mu[i] + Hb[i];
            mv_r = fh0 - atlb_r;
            Buf0[i][32] = mv_r;
        }
        if (isdiag || isv) { jn_r = Jb[16 + i]; hn_r = Hb[16 + i]; }
    }
    __syncthreads();

    float (*S)[48] = Buf0;
    float (*R)[48] = Buf1;

    // ======================= FORWARD (9 regions/step) =======================
    for (int t = 0; t < TM1; ++t) {
        float d0 = gj_block2<true>(S, R, 0,  i, j);
        float d1 = gj_block2<true>(R, S, 2,  i, j);
        float d2 = gj_block2<true>(S, R, 4,  i, j);
        float d3 = gj_block2<true>(R, S, 6,  i, j);
        float d4 = gj_block2<true>(S, R, 8,  i, j);
        float d5 = gj_block2<true>(R, S, 10, i, j);
        float d6 = gj_block2<true>(S, R, 12, i, j);
        float d7 = gj_block2<true>(R, S, 14, i, j);
        // S = [Pi | G | Mim]
        lzall += trans_const - 0.5f * (__logf(d0 * d1 * d2 * d3) + __logf(d4 * d5 * d6 * d7));

        const bool term = (t == TM1 - 1);
        scr1[(size_t)t * 256 + tid] = S[i][j];
        scr2[(size_t)t * 256 + tid] = S[i][16 + j];

        float na = lam_r, nb = 0.f;
#pragma unroll
        for (int k = 0; k < 8; ++k)  na = fmaf(-sAtL[k][i], S[k][16 + j], na);
#pragma unroll
        for (int k = 8; k < 16; ++k) nb = fmaf(-sAtL[k][i], S[k][16 + j], nb);
        R[i][j]      = (na + nb) + (isdiag ? (jn_r + 0.5f) : 0.f) + (term ? 0.f : atla_r);
        R[i][j + 16] = atl_r;

        if (isv) {
            float mim_i = S[i][32];
            scr3[(size_t)t * 16 + i] = mim_i;
            lzp += 0.5f * mv_r * mim_i;
            float fa = lb_r + hn_r, fb = 0.f;
#pragma unroll
            for (int k = 0; k < 8; ++k)  fa = fmaf(sAtL[k][i], S[k][32], fa);
#pragma unroll
            for (int k = 8; k < 16; ++k) fb = fmaf(sAtL[k][i], S[k][32], fb);
            float fh_new = fa + fb;
            mv_r = term ? fh_new : (fh_new - atlb_r);
            R[i][32] = mv_r;
        }
        if ((isdiag || isv) && (t + 2 < TT)) {
            jn_r = Jb[(t + 2) * 16 + i];
            hn_r = Hb[(t + 2) * 16 + i];
        }
        __syncthreads();
        float (*tmp)[48] = S; S = R; R = tmp;
    }

    // ---- terminal inversion: S holds [fJ_T | AtL | fh_T] ----
    {
        float d0 = gj_block2<true>(S, R, 0,  i, j);
        float d1 = gj_block2<true>(R, S, 2,  i, j);
        float d2 = gj_block2<true>(S, R, 4,  i, j);
        float d3 = gj_block2<true>(R, S, 6,  i, j);
        float d4 = gj_block2<true>(S, R, 8,  i, j);
        float d5 = gj_block2<true>(R, S, 10, i, j);
        float d6 = gj_block2<true>(S, R, 12, i, j);
        float d7 = gj_block2<true>(R, S, 14, i, j);
        lzall += init_const - 0.5f * (__logf(d0 * d1 * d2 * d3) + __logf(d4 * d5 * d6 * d7));
    }
    if (isv) {
        float mT = S[i][32];
        mT_s[i] = mT;
        lzp += 0.5f * mv_r * mT;
        exO[(size_t)(TT - 1) * 16 + i] = mT;
        scr3[(size_t)TM1 * 16 + i]     = mT;
    }
    __syncthreads();
    {
        float vT = S[i][j];
        float mTi = mT_s[i], mTj = mT_s[j];
        exxtO[(size_t)(TT - 1) * 256 + tid] = vT + mTi * mTj;
        Vn[i][j] = vT;
        if (isdiag) klacc += -0.5f * (jn_r + 0.5f) * (vT + mTi * mTi) + hn_r * mTi;
        if (isv) mn[i] = mT_s[i];
    }
    float g_r  = scr2[(size_t)(TM1 - 1) * 256 + tid];
    float pi_r = scr1[(size_t)(TM1 - 1) * 256 + tid];
    float mim_r = 0.f;
    if (isv)    mim_r = scr3[(size_t)(TM1 - 1) * 16 + i];
    if (isdiag) { jn_r = Jb[(TM1 - 1) * 16 + i]; hn_r = Hb[(TM1 - 1) * 16 + i]; }
    Gm[i][j] = g_r;
    __syncthreads();

    float v_reg = 0.f;
    // ======================= BACKWARD (20 regions/step) =======================
    for (int t = TM1 - 1; t >= 0; --t) {
        // R2: Wb = G Vn ; mt
        float wa = 0.f, wbp = 0.f;
#pragma unroll
        for (int k = 0; k < 8; ++k)  wa  = fmaf(Gm[i][k], Vn[k][j], wa);
#pragma unroll
        for (int k = 8; k < 16; ++k) wbp = fmaf(Gm[i][k], Vn[k][j], wbp);
        float w = wa + wbp;
        Wb[i][j] = w;
        if (isv) {
            float sa = mim_r, sb = 0.f;
#pragma unroll
            for (int k = 0; k < 8; ++k)  sa = fmaf(Gm[i][k], mn[k], sa);
#pragma unroll
            for (int k = 8; k < 16; ++k) sb = fmaf(Gm[i][k], mn[k], sb);
            mt_s[i] = sa + sb;
        }
        __syncthreads();                                   // b2

        // R3: Vt, outputs, stage GJ, klacc
        float va = pi_r, vb = 0.f;
#pragma unroll
        for (int k = 0; k < 8; ++k)  va = fmaf(Wb[i][k], Gm[j][k], va);
#pragma unroll
        for (int k = 8; k < 16; ++k) vb = fmaf(Wb[i][k], Gm[j][k], vb);
        float v = va + vb;
        v_reg = v;
        float mti = mt_s[i];
        exxtO [(size_t)t * 256 + tid] = v + mti * mt_s[j];
        exxntO[(size_t)t * 256 + tid] = w + mti * mn[j];
        if (isv) {
            exO[(size_t)t * 16 + i]  = mti;
            scr3[(size_t)t * 16 + i] = mti;
        }
        if (isdiag) klacc += -0.5f * (jn_r + 0.5f) * (v + mti * mti) + hn_r * mti;
        Buf0[i][j]      = v;
        Buf0[i][j + 16] = w;
        __syncthreads();                                   // b3

        gj_block2<false>(Buf0, Buf1, 0,  i, j);
        gj_block2<false>(Buf1, Buf0, 2,  i, j);
        gj_block2<false>(Buf0, Buf1, 4,  i, j);
        gj_block2<false>(Buf1, Buf0, 6,  i, j);
        gj_block2<false>(Buf0, Buf1, 8,  i, j);
        gj_block2<false>(Buf1, Buf0, 10, i, j);
        gj_block2<false>(Buf0, Buf1, 12, i, j);
        gj_block2<false>(Buf1, Buf0, 14, i, j);
        // Buf0 = [Vt^{-1} | K]

        // R8: condV, K^T store, stage chol
        float ca = Vn[i][j], cb = 0.f;
#pragma unroll
        for (int k = 0; k < 8; ++k)  ca = fmaf(-Wb[k][i], Buf0[k][16 + j], ca);
#pragma unroll
        for (int k = 8; k < 16; ++k) cb = fmaf(-Wb[k][i], Buf0[k][16 + j], cb);
        float cv = ca + cb;
        if (isdiag) cv += 1e-6f;
        scr1[(size_t)t * 256 + tid] = Buf0[j][16 + i];
        Buf1[i][j] = cv;
        __syncthreads();                                   // b8

        chol_block2(Buf1, Buf0, 0,  i, j);
        chol_block2(Buf0, Buf1, 2,  i, j);
        chol_block2(Buf1, Buf0, 4,  i, j);
        chol_block2(Buf0, Buf1, 6,  i, j);
        chol_block2(Buf1, Buf0, 8,  i, j);
        chol_block2(Buf0, Buf1, 10, i, j);
        chol_block2(Buf1, Buf0, 12, i, j);
        chol_block2(Buf0, Buf1, 14, i, j);
        // Buf1 = Ls

        // R1': Ls store, carry update, stage Gm, prefetch
        scr2[(size_t)t * 256 + tid] = (j <= i) ? Buf1[i][j] : 0.f;
        Vn[i][j] = v_reg;
        if (isv) mn[i] = mt_s[i];
        if (t > 0) {
            g_r  = scr2[(size_t)(t - 1) * 256 + tid];
            pi_r = scr1[(size_t)(t - 1) * 256 + tid];
            if (isv)    mim_r = scr3[(size_t)(t - 1) * 16 + i];
            if (isdiag) { jn_r = Jb[(t - 1) * 16 + i]; hn_r = Hb[(t - 1) * 16 + i]; }
            Gm[i][j] = g_r;
        }
        __syncthreads();                                   // b1
    }

    // ======================= SAMPLING =======================
    Buf0[i][j] = v_reg + (isdiag ? 1e-6f : 0.f);           // Vs[0] + jitter
    __syncthreads();
    chol_block2(Buf0, Buf1, 0,  i, j);
    chol_block2(Buf1, Buf0, 2,  i, j);
    chol_block2(Buf0, Buf1, 4,  i, j);
    chol_block2(Buf1, Buf0, 6,  i, j);
    chol_block2(Buf0, Buf1, 8,  i, j);
    chol_block2(Buf1, Buf0, 10, i, j);
    chol_block2(Buf0, Buf1, 12, i, j);
    chol_block2(Buf1, Buf0, 14, i, j);
    {
        float e0 = epsb[j];
        float v  = ((j <= i) ? Buf0[i][j] : 0.f) * e0;
        v += __shfl_xor_sync(0xffffffffu, v, 1);
        v += __shfl_xor_sync(0xffffffffu, v, 2);
        v += __shfl_xor_sync(0xffffffffu, v, 4);
        v += __shfl_xor_sync(0xffffffffu, v, 8);
        if (j == 0) { float x = mn[i] + v; xs[0][i] = x; zO[i] = x; }
    }
    __syncthreads();

    float kt_r  = scr1[tid];
    float ls_r  = scr2[tid];
    float mtj_r = scr3[j];
    float mni_r = scr3[16 + i];
    float ej_r  = epsb[16 + j];
    for (int t = 0; t < TM1; ++t) {
        float kt = kt_r, ls = ls_r, mtj = mtj_r, mni = mni_r, ej = ej_r;
        if (t + 1 < TM1) {
            kt_r  = scr1[(size_t)(t + 1) * 256 + tid];
            ls_r  = scr2[(size_t)(t + 1) * 256 + tid];
            mtj_r = scr3[(size_t)(t + 1) * 16 + j];
            mni_r = scr3[(size_t)(t + 2) * 16 + i];
            ej_r  = epsb[(size_t)(t + 2) * 16 + j];
        }
        float v = kt * (xs[t & 1][j] - mtj) + ls * ej;
        v += __shfl_xor_sync(0xffffffffu, v, 1);
        v += __shfl_xor_sync(0xffffffffu, v, 2);
        v += __shfl_xor_sync(0xffffffffu, v, 4);
        v += __shfl_xor_sync(0xffffffffu, v, 8);
        if (j == 0) {
            float x = mni + v;
            xs[(t & 1) ^ 1][i] = x;
            zO[(size_t)(t + 1) * 16 + i] = x;
        }
        __syncthreads();
    }

    // ---- final reductions ----
    if (isdiag) red[i]      = klacc;
    if (isv)    red[16 + i] = lzp;
    __syncthreads();
    if (tid == 0) {
        float kls = 0.f, lzs = 0.f;
#pragma unroll
        for (int k = 0; k < 16; ++k) { kls += red[k]; lzs += red[16 + k]; }
        out[KL_OFF + b] = kls - (lzall + lzs);
    }
}

extern "C" void kernel_launch(void* const* d_in, const int* in_sizes, int n_in,
                              void* d_out, int out_size) {
    const float* Jr    = (const float*)d_in[0];
    const float* hr    = (const float*)d_in[1];
    const float* loc   = (const float*)d_in[2];
    const float* Tau_p = (const float*)d_in[3];
    const float* Lam_p = (const float*)d_in[4];
    const float* X     = (const float*)d_in[5];
    float* out = (float*)d_out;

    setup_kernel<<<1, 256>>>(loc, Tau_p, Lam_p, X);
    lds_main<<<BB, 256>>>(Jr, hr, out);
}

// round 16
// speedup vs baseline: 1.2673x; 1.2673x over previous
#include <cuda_runtime.h>
#include <cstdint>

#define TT   1000
#define TM1  999
#define BB   64

__device__ __align__(16) float g_tau[256], g_lam[256], g_AtL[256], g_AtLA[256];
__device__ float g_tau_mu[16], g_AtLb[16], g_Lb[16];
__device__ float g_consts[2];
__device__ unsigned g_keys[BB][2];

__device__ __align__(16) float g_scr1[(size_t)BB * TM1 * 256]; // fwd: Pi -> bwd: K^T
__device__ __align__(16) float g_scr2[(size_t)BB * TM1 * 256]; // fwd: G  -> bwd: Ls
__device__ __align__(16) float g_scr3[(size_t)BB * TT  * 16];  // fwd: Mim-> bwd: m_t
__device__ __align__(16) float g_eps [(size_t)BB * TT  * 16];

__device__ __forceinline__ void tf2x32(unsigned k0, unsigned k1,
                                       unsigned x0, unsigned x1,
                                       unsigned &o0, unsigned &o1) {
    unsigned ks2 = k0 ^ k1 ^ 0x1BD11BDAu;
    x0 += k0; x1 += k1;
#define TFR(r) { x0 += x1; x1 = (x1 << (r)) | (x1 >> (32 - (r))); x1 ^= x0; }
    TFR(13) TFR(15) TFR(26) TFR(6)
    x0 += k1;  x1 += ks2 + 1u;
    TFR(17) TFR(29) TFR(16) TFR(24)
    x0 += ks2; x1 += k0 + 2u;
    TFR(13) TFR(15) TFR(26) TFR(6)
    x0 += k0;  x1 += k1 + 3u;
    TFR(17) TFR(29) TFR(16) TFR(24)
    x0 += k1;  x1 += ks2 + 4u;
    TFR(13) TFR(15) TFR(26) TFR(6)
    x0 += ks2; x1 += k0 + 5u;
#undef TFR
    o0 = x0; o1 = x1;
}

__device__ __forceinline__ float4 ld4(const float* p) {
    return *reinterpret_cast<const float4*>(p);
}
__device__ __forceinline__ void st4(float* p, float4 v) {
    *reinterpret_cast<float4*>(p) = v;
}

// ---- blocked GJ, 2 pivots [k,k+1]; 64 threads, thread=(row i, 4 cols j0..j0+3) ----
template <bool WITH_M>
__device__ __forceinline__ float gj2(const float (*C)[48], float (*N)[48],
                                     int k, int i, int j0, int q) {
    float p00 = C[k][k],     p01 = C[k][k + 1];
    float p10 = C[k + 1][k], p11 = C[k + 1][k + 1];
    float det = p00 * p11 - p01 * p10;
    float id  = __fdividef(1.f, det);
    float Di00 =  p11 * id, Di01 = -p01 * id;
    float Di10 = -p10 * id, Di11 =  p00 * id;
    float u0 = C[i][k], u1 = C[i][k + 1];
    bool ik = (i == k), ik1 = (i == k + 1);

    // left 4 cols
    {
        float4 a  = ld4(&C[i][j0]);
        float4 b0 = ld4(&C[k][j0]);
        float4 b1 = ld4(&C[k + 1][j0]);
        float res[4];
#pragma unroll
        for (int c = 0; c < 4; ++c) {
            float bb0 = (&b0.x)[c], bb1 = (&b1.x)[c], aa = (&a.x)[c];
            float w0 = Di00 * bb0 + Di01 * bb1;
            float w1 = Di10 * bb0 + Di11 * bb1;
            res[c] = ik ? w0 : (ik1 ? w1 : aa - (u0 * w0 + u1 * w1));
        }
        if (q == (k >> 2)) {           // pivot columns live in this thread's group
            int kc = k & 3;
            res[kc]     = ik ? Di00 : (ik1 ? Di10 : -(u0 * Di00 + u1 * Di10));
            res[kc + 1] = ik ? Di01 : (ik1 ? Di11 : -(u0 * Di01 + u1 * Di11));
        }
        st4(&N[i][j0], make_float4(res[0], res[1], res[2], res[3]));
    }
    // right 4 cols (never pivot)
    {
        float4 a  = ld4(&C[i][16 + j0]);
        float4 b0 = ld4(&C[k][16 + j0]);
        float4 b1 = ld4(&C[k + 1][16 + j0]);
        float res[4];
#pragma unroll
        for (int c = 0; c < 4; ++c) {
            float bb0 = (&b0.x)[c], bb1 = (&b1.x)[c], aa = (&a.x)[c];
            float w0 = Di00 * bb0 + Di01 * bb1;
            float w1 = Di10 * bb0 + Di11 * bb1;
            res[c] = ik ? w0 : (ik1 ? w1 : aa - (u0 * w0 + u1 * w1));
        }
        st4(&N[i][16 + j0], make_float4(res[0], res[1], res[2], res[3]));
    }
    if (WITH_M && q == 0) {
        float b0 = C[k][32], b1 = C[k + 1][32], am = C[i][32];
        float w0 = Di00 * b0 + Di01 * b1;
        float w1 = Di10 * b0 + Di11 * b1;
        N[i][32] = ik ? w0 : (ik1 ? w1 : am - (u0 * w0 + u1 * w1));
    }
    __syncthreads();
    return det;
}

// ---- blocked Cholesky (lower), 2 cols [k,k+1]; writes left 16 cols ----
__device__ __forceinline__ void chol2(const float (*C)[48], float (*N)[48],
                                      int k, int i, int j0) {
    float r0  = rsqrtf(C[k][k]);
    float l10 = C[k + 1][k] * r0;
    float t11 = C[k + 1][k + 1] - l10 * l10;
    float r1  = rsqrtf(t11);
    float p0 = C[i][k] * r0;
    float p1 = (C[i][k + 1] - p0 * l10) * r1;
    float4 a = ld4(&C[i][j0]);
    float res[4];
#pragma unroll
    for (int c = 0; c < 4; ++c) {
        int j = j0 + c;
        float r = (&a.x)[c];
        if (j == k)          { if (i >= k)     r = p0; }
        else if (j == k + 1) { if (i >= k + 1) r = p1; }
        else if (j > k + 1 && i >= j) {
            float q0 = C[j][k] * r0;
            float q1 = (C[j][k + 1] - q0 * l10) * r1;
            r = r - p0 * q0 - p1 * q1;
        }
        res[c] = r;
    }
    st4(&N[i][j0], make_float4(res[0], res[1], res[2], res[3]));
    __syncthreads();
}

__device__ float logdet16_local(const float M[16][17]) {
    float a[16][16];
    for (int r = 0; r < 16; ++r)
        for (int c = 0; c < 16; ++c) a[r][c] = M[r][c];
    float ld = 0.f;
    for (int k = 0; k < 16; ++k) {
        float p = a[k][k];
        ld += logf(p);
        float pi_ = __fdiv_rn(1.f, p);
        for (int r = k + 1; r < 16; ++r) {
            float f = a[r][k] * pi_;
            for (int c = k + 1; c < 16; ++c) a[r][c] = fmaf(-f, a[k][c], a[r][c]);
        }
    }
    return ld;
}

__global__ void __launch_bounds__(256) setup_kernel(const float* __restrict__ loc,
                                                    const float* __restrict__ Tau_p,
                                                    const float* __restrict__ Lam_p,
                                                    const float* __restrict__ X) {
    __shared__ float sTau[16][17], sLamS[16][17], sA[16][17], sAtLs[16][17];
    __shared__ float sbv[16], slocv[16];
    int tid = threadIdx.x, i = tid >> 4, j = tid & 15;

    float t = 0.f, l = 0.f;
#pragma unroll
    for (int k = 0; k < 16; ++k) {
        t = fmaf(Tau_p[i * 16 + k], Tau_p[j * 16 + k], t);
        l = fmaf(Lam_p[i * 16 + k], Lam_p[j * 16 + k], l);
    }
    if (i == j) { t += 1e-8f; l += 1e-8f; }
    sTau[i][j] = t; sLamS[i][j] = l;
    sA[i][j]   = X[i * 17 + j];
    if (tid < 16) { sbv[tid] = X[tid * 17 + 16]; slocv[tid] = loc[tid]; }
    __syncthreads();

    float atl = 0.f;
#pragma unroll
    for (int k = 0; k < 16; ++k) atl = fmaf(sA[k][i], sLamS[k][j], atl);
    sAtLs[i][j] = atl;
    __syncthreads();

    float atla = 0.f;
#pragma unroll
    for (int k = 0; k < 16; ++k) atla = fmaf(sAtLs[i][k], sA[k][j], atla);

    g_tau[tid] = t; g_lam[tid] = l; g_AtL[tid] = atl; g_AtLA[tid] = atla;

    if (tid < 16) {
        float tm = 0.f, alb = 0.f, lb = 0.f;
#pragma unroll
        for (int k = 0; k < 16; ++k) {
            tm  = fmaf(sTau[tid][k],  slocv[k], tm);
            alb = fmaf(sAtLs[tid][k], sbv[k],   alb);
            lb  = fmaf(sLamS[tid][k], sbv[k],   lb);
        }
        g_tau_mu[tid] = tm; g_AtLb[tid] = alb; g_Lb[tid] = lb;
    }
    if (tid < BB) {
        unsigned o0, o1;
        tf2x32(0u, 42u, 0u, (unsigned)tid, o0, o1);
        g_keys[tid][0] = o0; g_keys[tid][1] = o1;
    }
    __syncthreads();
    if (tid == 0) {
        float ldl = logdet16_local(sLamS);
        float ldt = logdet16_local(sTau);
        float bLb = 0.f, ltm = 0.f;
        for (int k = 0; k < 16; ++k) {
            bLb = fmaf(sbv[k],   g_Lb[k],     bLb);
            ltm = fmaf(slocv[k], g_tau_mu[k], ltm);
        }
        g_consts[0] = -0.5f * bLb + 0.5f * ldl;
        g_consts[1] = -0.5f * ltm + 0.5f * ldt;
    }
}

// =================== main: 64 threads (2 warps) per batch ===================
__global__ void __launch_bounds__(64, 1) lds_main(const float* __restrict__ Jr,
                                                  const float* __restrict__ hr,
                                                  float* __restrict__ out) {
    const int b   = blockIdx.x;
    const int tid = threadIdx.x;
    const int i   = tid >> 2;        // row 0..15
    const int q   = tid & 3;         // col group
    const int j0  = q * 4;
    const bool isq0   = (q == 0);
    const int  dc     = i & 3;
    const bool isdiag = (q == (i >> 2));   // owns diag element (i,i) at local col dc

    const float trans_const = g_consts[0];
    const float init_const  = g_consts[1];

    const float* Jb = Jr + (size_t)b * TT * 16;
    const float* Hb = hr + (size_t)b * TT * 16;
    float* scr1 = g_scr1 + (size_t)b * TM1 * 256;
    float* scr2 = g_scr2 + (size_t)b * TM1 * 256;
    float* scr3 = g_scr3 + (size_t)b * TT * 16;
    float* epsb = g_eps  + (size_t)b * TT * 16;

    const size_t KL_OFF    = (size_t)BB * TT * 16;
    const size_t EXXT_OFF  = KL_OFF + BB;
    const size_t EX_OFF    = EXXT_OFF + (size_t)BB * TT * 256;
    const size_t EXXNT_OFF = EX_OFF + (size_t)BB * TT * 16;
    float* zO     = out + (size_t)b * TT * 16;
    float* exxtO  = out + EXXT_OFF + (size_t)b * TT * 256;
    float* exO    = out + EX_OFF + (size_t)b * TT * 16;
    float* exxntO = out + EXXNT_OFF + (size_t)b * TM1 * 256;

    __shared__ __align__(16) float Buf0[16][48], Buf1[16][48];
    __shared__ __align__(16) float sAtL[16][20];
    __shared__ __align__(16) float Gm[16][20], Wb[16][20], Vn[16][20];
    __shared__ __align__(16) float mt_s[16], mn[16], mT_s[16];
    __shared__ __align__(16) float xs[2][16];
    __shared__ float red[32];

    // ---- epsilon generation ----
    {
        unsigned k0 = g_keys[b][0], k1 = g_keys[b][1];
        for (int idx = tid; idx < TT * 16; idx += 64) {
            unsigned o0, o1;
            tf2x32(k0, k1, 0u, (unsigned)idx, o0, o1);
            unsigned bits = o0 ^ o1;
            float f = __uint_as_float((bits >> 9) | 0x3f800000u) - 1.0f;
            const float lo = -0.99999994f;
            float v = fmaxf(lo, f * 2.0f + lo);
            epsb[idx] = 1.4142135623730951f * erfinvf(v);
        }
    }

    // ---- constants (registers, float4 per thread) ----
    float4 lam4  = ld4(&g_lam [i * 16 + j0]);
    float4 atla4 = ld4(&g_AtLA[i * 16 + j0]);
    float4 atl4  = ld4(&g_AtL [i * 16 + j0]);
    st4(&sAtL[i][j0], atl4);
    const float lb_r   = g_Lb[i];
    const float atlb_r = g_AtLb[i];

    float lzall = 0.f, lzp = 0.f, klacc = 0.f;
    float jn_r = 0.f, hn_r = 0.f, mv_r = 0.f;

    // ---- pre-stage step 0 ----
    {
        float4 tau4 = ld4(&g_tau[i * 16 + j0]);
        if (isdiag) (&tau4.x)[dc] += Jb[i] + 0.5f;
        float4 m0;
        m0.x = tau4.x + atla4.x; m0.y = tau4.y + atla4.y;
        m0.z = tau4.z + atla4.z; m0.w = tau4.w + atla4.w;
        st4(&Buf0[i][j0], m0);
        st4(&Buf0[i][16 + j0], atl4);
        if (isq0) {
            mv_r = g_tau_mu[i] + Hb[i] - atlb_r;
            Buf0[i][32] = mv_r;
        }
        if (isdiag || isq0) { jn_r = Jb[16 + i]; hn_r = Hb[16 + i]; }
    }
    __syncthreads();

    float (*S)[48] = Buf0;
    float (*R)[48] = Buf1;

    // ======================= FORWARD =======================
    for (int t = 0; t < TM1; ++t) {
        float d0 = gj2<true>(S, R, 0,  i, j0, q);
        float d1 = gj2<true>(R, S, 2,  i, j0, q);
        float d2 = gj2<true>(S, R, 4,  i, j0, q);
        float d3 = gj2<true>(R, S, 6,  i, j0, q);
        float d4 = gj2<true>(S, R, 8,  i, j0, q);
        float d5 = gj2<true>(R, S, 10, i, j0, q);
        float d6 = gj2<true>(S, R, 12, i, j0, q);
        float d7 = gj2<true>(R, S, 14, i, j0, q);
        lzall += trans_const - 0.5f * (__logf(d0 * d1 * d2 * d3) + __logf(d4 * d5 * d6 * d7));

        const bool term = (t == TM1 - 1);
        st4(&scr1[(size_t)t * 256 + i * 16 + j0], ld4(&S[i][j0]));
        st4(&scr2[(size_t)t * 256 + i * 16 + j0], ld4(&S[i][16 + j0]));

        float4 acc = lam4;
#pragma unroll
        for (int k = 0; k < 16; ++k) {
            float a = sAtL[k][i];
            float4 s = ld4(&S[k][16 + j0]);
            acc.x = fmaf(-a, s.x, acc.x);
            acc.y = fmaf(-a, s.y, acc.y);
            acc.z = fmaf(-a, s.z, acc.z);
            acc.w = fmaf(-a, s.w, acc.w);
        }
        if (isdiag) (&acc.x)[dc] += jn_r + 0.5f;
        if (!term) {
            acc.x += atla4.x; acc.y += atla4.y; acc.z += atla4.z; acc.w += atla4.w;
        }
        st4(&R[i][j0], acc);
        st4(&R[i][16 + j0], atl4);

        if (isq0) {
            float mim_i = S[i][32];
            scr3[(size_t)t * 16 + i] = mim_i;
            lzp += 0.5f * mv_r * mim_i;
            float s = lb_r + hn_r;
#pragma unroll
            for (int k = 0; k < 16; ++k) s = fmaf(sAtL[k][i], S[k][32], s);
            mv_r = term ? s : (s - atlb_r);
            R[i][32] = mv_r;
        }
        if ((isdiag || isq0) && (t + 2 < TT)) {
            jn_r = Jb[(t + 2) * 16 + i];
            hn_r = Hb[(t + 2) * 16 + i];
        }
        __syncthreads();
        float (*tmp)[48] = S; S = R; R = tmp;
    }

    // ---- terminal inversion ----
    {
        float d0 = gj2<true>(S, R, 0,  i, j0, q);
        float d1 = gj2<true>(R, S, 2,  i, j0, q);
        float d2 = gj2<true>(S, R, 4,  i, j0, q);
        float d3 = gj2<true>(R, S, 6,  i, j0, q);
        float d4 = gj2<true>(S, R, 8,  i, j0, q);
        float d5 = gj2<true>(R, S, 10, i, j0, q);
        float d6 = gj2<true>(S, R, 12, i, j0, q);
        float d7 = gj2<true>(R, S, 14, i, j0, q);
        lzall += init_const - 0.5f * (__logf(d0 * d1 * d2 * d3) + __logf(d4 * d5 * d6 * d7));
    }
    if (isq0) {
        float mT = S[i][32];
        mT_s[i] = mT;
        lzp += 0.5f * mv_r * mT;
        exO[(size_t)(TT - 1) * 16 + i] = mT;
        scr3[(size_t)TM1 * 16 + i]     = mT;
    }
    __syncthreads();
    {
        float4 vT4 = ld4(&S[i][j0]);
        float mTi = mT_s[i];
        float4 mTj4 = ld4(&mT_s[j0]);
        float4 ex;
        ex.x = vT4.x + mTi * mTj4.x; ex.y = vT4.y + mTi * mTj4.y;
        ex.z = vT4.z + mTi * mTj4.z; ex.w = vT4.w + mTi * mTj4.w;
        st4(&exxtO[(size_t)(TT - 1) * 256 + i * 16 + j0], ex);
        st4(&Vn[i][j0], vT4);
        if (isdiag) klacc += -0.5f * (jn_r + 0.5f) * ((&vT4.x)[dc] + mTi * mTi) + hn_r * mTi;
        if (isq0) mn[i] = mT_s[i];
    }
    float4 g4p  = ld4(&scr2[(size_t)(TM1 - 1) * 256 + i * 16 + j0]);
    float4 pi4p = ld4(&scr1[(size_t)(TM1 - 1) * 256 + i * 16 + j0]);
    float mim_r = 0.f;
    if (isq0)   mim_r = scr3[(size_t)(TM1 - 1) * 16 + i];
    if (isdiag || isq0) { jn_r = Jb[(TM1 - 1) * 16 + i]; hn_r = Hb[(TM1 - 1) * 16 + i]; }
    st4(&Gm[i][j0], g4p);
    __syncthreads();

    float4 v4_keep = make_float4(0.f, 0.f, 0.f, 0.f);
    // ======================= BACKWARD =======================
    for (int t = TM1 - 1; t >= 0; --t) {
        // R2: Wb = G Vn ; mt
        float4 gm0 = ld4(&Gm[i][0]), gm1 = ld4(&Gm[i][4]);
        float4 gm2 = ld4(&Gm[i][8]), gm3 = ld4(&Gm[i][12]);
        float gmr[16] = {gm0.x,gm0.y,gm0.z,gm0.w, gm1.x,gm1.y,gm1.z,gm1.w,
                         gm2.x,gm2.y,gm2.z,gm2.w, gm3.x,gm3.y,gm3.z,gm3.w};
        float4 w4 = make_float4(0.f, 0.f, 0.f, 0.f);
#pragma unroll
        for (int k = 0; k < 16; ++k) {
            float gk = gmr[k];
            float4 vk = ld4(&Vn[k][j0]);
            w4.x = fmaf(gk, vk.x, w4.x); w4.y = fmaf(gk, vk.y, w4.y);
            w4.z = fmaf(gk, vk.z, w4.z); w4.w = fmaf(gk, vk.w, w4.w);
        }
        st4(&Wb[i][j0], w4);
        if (isq0) {
            float s = mim_r;
#pragma unroll
            for (int k = 0; k < 16; ++k) s = fmaf(gmr[k], mn[k], s);
            mt_s[i] = s;
        }
        __syncthreads();                                   // b2

        // R3: Vt, outputs, stage GJ, klacc
        float4 wb0 = ld4(&Wb[i][0]), wb1 = ld4(&Wb[i][4]);
        float4 wb2 = ld4(&Wb[i][8]), wb3 = ld4(&Wb[i][12]);
        float wbr[16] = {wb0.x,wb0.y,wb0.z,wb0.w, wb1.x,wb1.y,wb1.z,wb1.w,
                         wb2.x,wb2.y,wb2.z,wb2.w, wb3.x,wb3.y,wb3.z,wb3.w};
        float vv[4];
#pragma unroll
        for (int c = 0; c < 4; ++c) {
            int row = j0 + c;
            float4 ga = ld4(&Gm[row][0]), gb = ld4(&Gm[row][4]);
            float4 gc = ld4(&Gm[row][8]), gd = ld4(&Gm[row][12]);
            float s = (&pi4p.x)[c];
            s = fmaf(wbr[0], ga.x, s); s = fmaf(wbr[1], ga.y, s);
            s = fmaf(wbr[2], ga.z, s); s = fmaf(wbr[3], ga.w, s);
            s = fmaf(wbr[4], gb.x, s); s = fmaf(wbr[5], gb.y, s);
            s = fmaf(wbr[6], gb.z, s); s = fmaf(wbr[7], gb.w, s);
            s = fmaf(wbr[8], gc.x, s); s = fmaf(wbr[9], gc.y, s);
            s = fmaf(wbr[10], gc.z, s); s = fmaf(wbr[11], gc.w, s);
            s = fmaf(wbr[12], gd.x, s); s = fmaf(wbr[13], gd.y, s);
            s = fmaf(wbr[14], gd.z, s); s = fmaf(wbr[15], gd.w, s);
            vv[c] = s;
        }
        float4 v4 = make_float4(vv[0], vv[1], vv[2], vv[3]);
        v4_keep = v4;
        float mti = mt_s[i];
        float4 mtj4 = ld4(&mt_s[j0]);
        float4 mn4  = ld4(&mn[j0]);
        float4 ex, en;
        ex.x = v4.x + mti * mtj4.x; ex.y = v4.y + mti * mtj4.y;
        ex.z = v4.z + mti * mtj4.z; ex.w = v4.w + mti * mtj4.w;
        en.x = w4.x + mti * mn4.x;  en.y = w4.y + mti * mn4.y;
        en.z = w4.z + mti * mn4.z;  en.w = w4.w + mti * mn4.w;
        st4(&exxtO [(size_t)t * 256 + i * 16 + j0], ex);
        st4(&exxntO[(size_t)t * 256 + i * 16 + j0], en);
        if (isq0) {
            exO[(size_t)t * 16 + i]  = mti;
            scr3[(size_t)t * 16 + i] = mti;
        }
        if (isdiag) klacc += -0.5f * (jn_r + 0.5f) * ((&v4.x)[dc] + mti * mti) + hn_r * mti;
        st4(&Buf0[i][j0], v4);
        st4(&Buf0[i][16 + j0], w4);
        __syncthreads();                                   // b3

        gj2<false>(Buf0, Buf1, 0,  i, j0, q);
        gj2<false>(Buf1, Buf0, 2,  i, j0, q);
        gj2<false>(Buf0, Buf1, 4,  i, j0, q);
        gj2<false>(Buf1, Buf0, 6,  i, j0, q);
        gj2<false>(Buf0, Buf1, 8,  i, j0, q);
        gj2<false>(Buf1, Buf0, 10, i, j0, q);
        gj2<false>(Buf0, Buf1, 12, i, j0, q);
        gj2<false>(Buf1, Buf0, 14, i, j0, q);
        // Buf0 = [Vt^{-1} | K]

        // R8: condV, K^T store, stage chol
        float4 c4 = ld4(&Vn[i][j0]);
#pragma unroll
        for (int k = 0; k < 16; ++k) {
            float wk = Wb[k][i];
            float4 kk = ld4(&Buf0[k][16 + j0]);
            c4.x = fmaf(-wk, kk.x, c4.x); c4.y = fmaf(-wk, kk.y, c4.y);
            c4.z = fmaf(-wk, kk.z, c4.z); c4.w = fmaf(-wk, kk.w, c4.w);
        }
        if (isdiag) (&c4.x)[dc] += 1e-6f;
        {
            float4 kt;
            kt.x = Buf0[j0][16 + i];     kt.y = Buf0[j0 + 1][16 + i];
            kt.z = Buf0[j0 + 2][16 + i]; kt.w = Buf0[j0 + 3][16 + i];
            st4(&scr1[(size_t)t * 256 + i * 16 + j0], kt);
        }
        st4(&Buf1[i][j0], c4);
        __syncthreads();                                   // b8

        chol2(Buf1, Buf0, 0,  i, j0);
        chol2(Buf0, Buf1, 2,  i, j0);
        chol2(Buf1, Buf0, 4,  i, j0);
        chol2(Buf0, Buf1, 6,  i, j0);
        chol2(Buf1, Buf0, 8,  i, j0);
        chol2(Buf0, Buf1, 10, i, j0);
        chol2(Buf1, Buf0, 12, i, j0);
        chol2(Buf0, Buf1, 14, i, j0);
        // Buf1 = Ls

        // last region: Ls store, carry, prefetch
        {
            float4 ls = ld4(&Buf1[i][j0]);
            if (j0 > i)          ls.x = 0.f;
            if (j0 + 1 > i)      ls.y = 0.f;
            if (j0 + 2 > i)      ls.z = 0.f;
            if (j0 + 3 > i)      ls.w = 0.f;
            st4(&scr2[(size_t)t * 256 + i * 16 + j0], ls);
        }
        st4(&Vn[i][j0], v4_keep);
        if (isq0) mn[i] = mt_s[i];
        if (t > 0) {
            g4p  = ld4(&scr2[(size_t)(t - 1) * 256 + i * 16 + j0]);
            pi4p = ld4(&scr1[(size_t)(t - 1) * 256 + i * 16 + j0]);
            if (isq0)   mim_r = scr3[(size_t)(t - 1) * 16 + i];
            if (isdiag || isq0) { jn_r = Jb[(t - 1) * 16 + i]; hn_r = Hb[(t - 1) * 16 + i]; }
            st4(&Gm[i][j0], g4p);
        }
        __syncthreads();                                   // b1
    }

    // ======================= SAMPLING =======================
    {
        float4 v0 = ld4(&Vn[i][j0]);
        if (isdiag) (&v0.x)[dc] += 1e-6f;
        st4(&Buf0[i][j0], v0);
    }
    __syncthreads();
    chol2(Buf0, Buf1, 0,  i, j0);
    chol2(Buf1, Buf0, 2,  i, j0);
    chol2(Buf0, Buf1, 4,  i, j0);
    chol2(Buf1, Buf0, 6,  i, j0);
    chol2(Buf0, Buf1, 8,  i, j0);
    chol2(Buf1, Buf0, 10, i, j0);
    chol2(Buf0, Buf1, 12, i, j0);
    chol2(Buf1, Buf0, 14, i, j0);
    {
        float4 l4 = ld4(&Buf0[i][j0]);
        float4 e4 = ld4(&epsb[j0]);
        float v = 0.f;
        if (j0     <= i) v = fmaf(l4.x, e4.x, v);
        if (j0 + 1 <= i) v = fmaf(l4.y, e4.y, v);
        if (j0 + 2 <= i) v = fmaf(l4.z, e4.z, v);
        if (j0 + 3 <= i) v = fmaf(l4.w, e4.w, v);
        v += __shfl_xor_sync(0xffffffffu, v, 1);
        v += __shfl_xor_sync(0xffffffffu, v, 2);
        if (isq0) { float x = mn[i] + v; xs[0][i] = x; zO[i] = x; }
    }
    __syncthreads();

    float4 kt4  = ld4(&scr1[i * 16 + j0]);
    float4 ls4  = ld4(&scr2[i * 16 + j0]);
    float4 mtj4 = ld4(&scr3[j0]);
    float  mni  = scr3[16 + i];
    float4 ej4  = ld4(&epsb[16 + j0]);
    for (int t = 0; t < TM1; ++t) {
        float4 kt = kt4, ls = ls4, mtj = mtj4, ej = ej4;
        float mnc = mni;
        if (t + 1 < TM1) {
            kt4  = ld4(&scr1[(size_t)(t + 1) * 256 + i * 16 + j0]);
            ls4  = ld4(&scr2[(size_t)(t + 1) * 256 + i * 16 + j0]);
            mtj4 = ld4(&scr3[(size_t)(t + 1) * 16 + j0]);
            mni  = scr3[(size_t)(t + 2) * 16 + i];
            ej4  = ld4(&epsb[(size_t)(t + 2) * 16 + j0]);
        }
        float4 x4 = ld4(&xs[t & 1][j0]);
        float v = 0.f;
        v = fmaf(kt.x, x4.x - mtj.x, v); v = fmaf(ls.x, ej.x, v);
        v = fmaf(kt.y, x4.y - mtj.y, v); v = fmaf(ls.y, ej.y, v);
        v = fmaf(kt.z, x4.z - mtj.z, v); v = fmaf(ls.z, ej.z, v);
        v = fmaf(kt.w, x4.w - mtj.w, v); v = fmaf(ls.w, ej.w, v);
        v += __shfl_xor_sync(0xffffffffu, v, 1);
        v += __shfl_xor_sync(0xffffffffu, v, 2);
        if (isq0) {
            float x = mnc + v;
            xs[(t & 1) ^ 1][i] = x;
            zO[(size_t)(t + 1) * 16 + i] = x;
        }
        __syncthreads();
    }

    // ---- final reductions ----
    if (isdiag) red[i]      = klacc;
    if (isq0)   red[16 + i] = lzp;
    __syncthreads();
    if (tid == 0) {
        float kls = 0.f, lzs = 0.f;
#pragma unroll
        for (int k = 0; k < 16; ++k) { kls += red[k]; lzs += red[16 + k]; }
        out[KL_OFF + b] = kls - (lzall + lzs);
    }
}

extern "C" void kernel_launch(void* const* d_in, const int* in_sizes, int n_in,
                              void* d_out, int out_size) {
    const float* Jr    = (const float*)d_in[0];
    const float* hr    = (const float*)d_in[1];
    const float* loc   = (const float*)d_in[2];
    const float* Tau_p = (const float*)d_in[3];
    const float* Lam_p = (const float*)d_in[4];
    const float* X     = (const float*)d_in[5];
    float* out = (float*)d_out;

    setup_kernel<<<1, 256>>>(loc, Tau_p, Lam_p, X);
    lds_main<<<BB, 64>>>(Jr, hr, out);
}